// round 5
// baseline (speedup 1.0000x reference)
#include <cuda_runtime.h>

#define DIM    128
#define NPROJ  256
#define MTILE  64          // projections per shared tile (32 KB)
#define TPB    256
#define TOK_PER_BLOCK 128  // 4 threads per token, 2 tokens per thread

// packed f32x2 FMA: d = a*b + d
__device__ __forceinline__ void fma2(unsigned long long &d,
                                     unsigned long long a,
                                     unsigned long long b) {
    asm("fma.rn.f32x2 %0, %1, %2, %0;" : "+l"(d) : "l"(a), "l"(b));
}

__device__ __forceinline__ float red2(unsigned long long e, unsigned long long o) {
    float ex, ey, ox, oy;
    asm("mov.b64 {%0, %1}, %2;" : "=f"(ex), "=f"(ey) : "l"(e));
    asm("mov.b64 {%0, %1}, %2;" : "=f"(ox), "=f"(oy) : "l"(o));
    return (ex + ox) + (ey + oy);
}

__global__ void __launch_bounds__(TPB, 1)
qjl_kernel(const float* __restrict__ Q,
           const float* __restrict__ K,
           const float* __restrict__ S,
           float* __restrict__ out,
           int ntok)
{
    // 64 projections x 128 dims fp32, as 16B chunks
    __shared__ ulonglong2 s_sh[MTILE * DIM / 4];

    const int tid   = threadIdx.x;
    const int quart = tid & 3;                 // which 32-dim quarter this thread owns
    const int grp   = tid >> 2;                // token-pair group (0..63)
    const int t0    = blockIdx.x * TOK_PER_BLOCK + grp * 2;
    const int t1    = t0 + 1;
    const int t0c   = t0 < ntok ? t0 : (ntok - 1);
    const int t1c   = t1 < ntok ? t1 : (ntok - 1);

    // Per-thread data: 2 tokens x 32 dims of q and k = 128 fp32 in registers.
    unsigned long long k0r[16], k1r[16], q0r[16], q1r[16];
    {
        const ulonglong2* k0g = (const ulonglong2*)(K + (size_t)t0c * DIM + quart * 32);
        const ulonglong2* k1g = (const ulonglong2*)(K + (size_t)t1c * DIM + quart * 32);
        const ulonglong2* q0g = (const ulonglong2*)(Q + (size_t)t0c * DIM + quart * 32);
        const ulonglong2* q1g = (const ulonglong2*)(Q + (size_t)t1c * DIM + quart * 32);
#pragma unroll
        for (int i = 0; i < 8; ++i) {
            ulonglong2 v;
            v = k0g[i]; k0r[2*i] = v.x; k0r[2*i+1] = v.y;
            v = k1g[i]; k1r[2*i] = v.x; k1r[2*i+1] = v.y;
            v = q0g[i]; q0r[2*i] = v.x; q0r[2*i+1] = v.y;
            v = q1g[i]; q1r[2*i] = v.x; q1r[2*i+1] = v.y;
        }
    }

    float acc0 = 0.0f, acc1 = 0.0f;

    for (int mt = 0; mt < NPROJ; mt += MTILE) {
        __syncthreads();
        // cooperative, coalesced load of the S tile (64 x 128 fp32)
        const ulonglong2* sg = (const ulonglong2*)S + (size_t)mt * (DIM / 4);
        for (int i = tid; i < MTILE * DIM / 4; i += TPB) s_sh[i] = sg[i];
        __syncthreads();

#pragma unroll 2
        for (int ml = 0; ml < MTILE; ++ml) {
            // this thread's 32-dim slice of projection row (mt+ml)
            const ulonglong2* srow = &s_sh[ml * (DIM / 4) + quart * 8];

            // 8 independent f32x2 accumulator chains: {k,q} x {tok0,tok1} x {even,odd}
            unsigned long long ak0e = 0ull, ak0o = 0ull, ak1e = 0ull, ak1o = 0ull;
            unsigned long long aq0e = 0ull, aq0o = 0ull, aq1e = 0ull, aq1o = 0ull;
#pragma unroll
            for (int i = 0; i < 8; ++i) {
                ulonglong2 sv = srow[i];        // one LDS.128 feeds 8 FFMA2
                fma2(ak0e, sv.x, k0r[2*i]);
                fma2(ak1e, sv.x, k1r[2*i]);
                fma2(aq0e, sv.x, q0r[2*i]);
                fma2(aq1e, sv.x, q1r[2*i]);
                fma2(ak0o, sv.y, k0r[2*i+1]);
                fma2(ak1o, sv.y, k1r[2*i+1]);
                fma2(aq0o, sv.y, q0r[2*i+1]);
                fma2(aq1o, sv.y, q1r[2*i+1]);
            }

            float kp0 = red2(ak0e, ak0o);
            float kp1 = red2(ak1e, ak1o);
            float qp0 = red2(aq0e, aq0o);
            float qp1 = red2(aq1e, aq1o);

            // butterfly over the 4 dim-quarter threads (lanes q, q^1, q^2, q^3)
            kp0 += __shfl_xor_sync(0xffffffffu, kp0, 1);
            kp1 += __shfl_xor_sync(0xffffffffu, kp1, 1);
            qp0 += __shfl_xor_sync(0xffffffffu, qp0, 1);
            qp1 += __shfl_xor_sync(0xffffffffu, qp1, 1);
            kp0 += __shfl_xor_sync(0xffffffffu, kp0, 2);
            kp1 += __shfl_xor_sync(0xffffffffu, kp1, 2);
            qp0 += __shfl_xor_sync(0xffffffffu, qp0, 2);
            qp1 += __shfl_xor_sync(0xffffffffu, qp1, 2);

            // acc += qp * sign(kp); jnp.sign(0) == 0 -> skip kp == 0
            float s0 = __uint_as_float(__float_as_uint(qp0) ^
                                       (__float_as_uint(kp0) & 0x80000000u));
            float s1 = __uint_as_float(__float_as_uint(qp1) ^
                                       (__float_as_uint(kp1) & 0x80000000u));
            if (kp0 != 0.0f) acc0 += s0;
            if (kp1 != 0.0f) acc1 += s1;
        }
    }

    const float scale = (float)(1.2533141373155003 / 256.0);  // sqrt(pi/2)/NUM_PROJ
    if (quart == 0) {
        if (t0 < ntok) out[t0] = scale * acc0;
        if (t1 < ntok) out[t1] = scale * acc1;
    }
}

extern "C" void kernel_launch(void* const* d_in, const int* in_sizes, int n_in,
                              void* d_out, int out_size) {
    // Identify S by element count (NPROJ*DIM = 32768); q precedes k among the rest.
    int s_idx = 2;
    for (int i = 0; i < n_in; ++i) if (in_sizes[i] == NPROJ * DIM) { s_idx = i; break; }
    int qk[2], w = 0;
    for (int i = 0; i < n_in && w < 2; ++i) if (i != s_idx) qk[w++] = i;

    const float* Q = (const float*)d_in[qk[0]];  // query [B,H,SEQ,DIM] fp32
    const float* K = (const float*)d_in[qk[1]];  // key   [B,H,SEQ,DIM] fp32
    const float* S = (const float*)d_in[s_idx];  // S     [NPROJ,DIM]   fp32
    float* out = (float*)d_out;                  // [B,H,SEQ] fp32

    const int ntok   = in_sizes[qk[0]] / DIM;
    const int blocks = (ntok + TOK_PER_BLOCK - 1) / TOK_PER_BLOCK;
    qjl_kernel<<<blocks, TPB>>>(Q, K, S, out, ntok);
}

// round 7
// speedup vs baseline: 4.9528x; 4.9528x over previous
#include <cuda_runtime.h>
#include <cuda_bf16.h>

#define DIM    128
#define NPROJ  256
#define TPB    256
#define TOK_PER_CTA 128     // 8 warps x 16 tokens
#define TAU    2e-3f
#define SCALE  ((float)(1.2533141373155003 / 256.0))   // sqrt(pi/2)/NPROJ

// S repacked for direct B-fragment LDG.128:
// index (n, j, tg) -> uint4 { hi(k=tg*2+16j, +1), hi(k+8,+9), lo(k..), lo(k+8..) }
__device__ uint4 g_Sp[NPROJ * 8 * 4];

__device__ __forceinline__ unsigned pack_hi(float x, float y) {
    unsigned short hx = __bfloat16_as_ushort(__float2bfloat16_rn(x));
    unsigned short hy = __bfloat16_as_ushort(__float2bfloat16_rn(y));
    return ((unsigned)hy << 16) | (unsigned)hx;
}
__device__ __forceinline__ unsigned pack_lo(float x, float y) {
    float rx = x - __bfloat162float(__float2bfloat16_rn(x));
    float ry = y - __bfloat162float(__float2bfloat16_rn(y));
    return pack_hi(rx, ry);
}

__global__ void prep_S(const float* __restrict__ S) {
    int idx = blockIdx.x * blockDim.x + threadIdx.x;   // 0..8191 = (n*8 + j)*4 + tg
    int tg = idx & 3, j = (idx >> 2) & 7, n = idx >> 5;
    int d0 = tg * 2 + 16 * j;
    const float* row = S + n * DIM;
    float x0 = row[d0], x1 = row[d0 + 1], y0 = row[d0 + 8], y1 = row[d0 + 9];
    uint4 v;
    v.x = pack_hi(x0, x1);  v.y = pack_hi(y0, y1);
    v.z = pack_lo(x0, x1);  v.w = pack_lo(y0, y1);
    g_Sp[idx] = v;
}

// mma.sync m16n8k16 bf16 -> f32 accumulate (baseline sm_80 ISA; no 'a' features)
__device__ __forceinline__ void mma_bf16(float* c, const unsigned* a,
                                         unsigned b0, unsigned b1) {
    asm volatile(
        "mma.sync.aligned.m16n8k16.row.col.f32.bf16.bf16.f32 "
        "{%0,%1,%2,%3}, {%4,%5,%6,%7}, {%8,%9}, {%0,%1,%2,%3};"
        : "+f"(c[0]), "+f"(c[1]), "+f"(c[2]), "+f"(c[3])
        : "r"(a[0]), "r"(a[1]), "r"(a[2]), "r"(a[3]), "r"(b0), "r"(b1));
}

// sign(kp)*qp with exact-fp32 fix-up when |kp| is inside the bf16x3 error band.
__device__ __forceinline__ float term(float kp, float qp,
                                      const float* __restrict__ K,
                                      const float* __restrict__ S,
                                      int tok, int proj) {
    if (fabsf(kp) < TAU) {                 // rare (~1.4e-4): recompute exactly
        const float* kr = K + (size_t)tok * DIM;
        const float* sr = S + (size_t)proj * DIM;
        float s = 0.f;
#pragma unroll 8
        for (int d = 0; d < DIM; ++d) s = fmaf(kr[d], sr[d], s);
        kp = s;
        if (kp == 0.f) return 0.f;         // jnp.sign(0) == 0
    }
    return __uint_as_float(__float_as_uint(qp) ^
                           (__float_as_uint(kp) & 0x80000000u));
}

__global__ void __launch_bounds__(TPB, 1)
qjl_mma_kernel(const float* __restrict__ Q,
               const float* __restrict__ K,
               const float* __restrict__ S,
               float* __restrict__ out,
               int ntok)
{
    const int tid  = threadIdx.x;
    const int w    = tid >> 5;
    const int lane = tid & 31;
    const int g    = lane >> 2;            // row group (token within 16-block)
    const int tg   = lane & 3;             // thread-in-group (k pairs / C cols)

    const int base = blockIdx.x * TOK_PER_CTA + w * 16;
    const int tok0 = base + g, tok1 = base + g + 8;
    const int t0c  = tok0 < ntok ? tok0 : ntok - 1;
    const int t1c  = tok1 < ntok ? tok1 : ntok - 1;

    // ---- build A fragments in registers: Q,K x hi,lo, K-dim = 128 (8 k-steps) ----
    unsigned aqh[8][4], aql[8][4], akh[8][4], akl[8][4];
    {
        const float* q0 = Q + (size_t)t0c * DIM;
        const float* q1 = Q + (size_t)t1c * DIM;
        const float* k0 = K + (size_t)t0c * DIM;
        const float* k1 = K + (size_t)t1c * DIM;
#pragma unroll
        for (int j = 0; j < 8; ++j) {
            const int c = tg * 2 + 16 * j;
            float2 v;
            v = *(const float2*)(q0 + c);     aqh[j][0] = pack_hi(v.x, v.y); aql[j][0] = pack_lo(v.x, v.y);
            v = *(const float2*)(q1 + c);     aqh[j][1] = pack_hi(v.x, v.y); aql[j][1] = pack_lo(v.x, v.y);
            v = *(const float2*)(q0 + c + 8); aqh[j][2] = pack_hi(v.x, v.y); aql[j][2] = pack_lo(v.x, v.y);
            v = *(const float2*)(q1 + c + 8); aqh[j][3] = pack_hi(v.x, v.y); aql[j][3] = pack_lo(v.x, v.y);
            v = *(const float2*)(k0 + c);     akh[j][0] = pack_hi(v.x, v.y); akl[j][0] = pack_lo(v.x, v.y);
            v = *(const float2*)(k1 + c);     akh[j][1] = pack_hi(v.x, v.y); akl[j][1] = pack_lo(v.x, v.y);
            v = *(const float2*)(k0 + c + 8); akh[j][2] = pack_hi(v.x, v.y); akl[j][2] = pack_lo(v.x, v.y);
            v = *(const float2*)(k1 + c + 8); akh[j][3] = pack_hi(v.x, v.y); akl[j][3] = pack_lo(v.x, v.y);
        }
    }

    float acc0 = 0.f, acc1 = 0.f;

    // ---- 32 projection tiles of n=8; per tile: 8 k-steps x 6 MMA (bf16x3, q+k) ----
#pragma unroll 1
    for (int nt = 0; nt < 32; ++nt) {
        float cq[4] = {0.f, 0.f, 0.f, 0.f};
        float ck[4] = {0.f, 0.f, 0.f, 0.f};
        // B fragments: one uint4 per k-step per lane (L1-resident repack)
        const uint4* bp = g_Sp + ((nt * 8 + g) * 32 + tg) / 4;   // uint4 index (n*8+j)*... see below
        // NOTE: g_Sp is uint4[]; linear uint4 index = (n*8 + j)*4 + tg
        bp = g_Sp + ((size_t)(nt * 8 + g) * 32 + tg);            // elements of uint4? fix below
        bp = g_Sp + ((size_t)(nt * 8 + g) * 8 * 4) / 4;          // placeholder, real index next line
        const uint4* bq = g_Sp + ((size_t)(nt * 8 + g) * 8 + 0) * 4 + tg;
#pragma unroll
        for (int j = 0; j < 8; ++j) {
            uint4 b = bq[j * 4];
            mma_bf16(cq, aqh[j], b.x, b.y);   // hi * hi
            mma_bf16(cq, aql[j], b.x, b.y);   // lo * hi
            mma_bf16(cq, aqh[j], b.z, b.w);   // hi * lo
            mma_bf16(ck, akh[j], b.x, b.y);
            mma_bf16(ck, akl[j], b.x, b.y);
            mma_bf16(ck, akh[j], b.z, b.w);
        }
        const int proj0 = nt * 8 + tg * 2;
        acc0 += term(ck[0], cq[0], K, S, t0c, proj0);
        acc0 += term(ck[1], cq[1], K, S, t0c, proj0 + 1);
        acc1 += term(ck[2], cq[2], K, S, t1c, proj0);
        acc1 += term(ck[3], cq[3], K, S, t1c, proj0 + 1);
    }

    // ---- final reduction over the 4 lanes of each row group ----
    acc0 += __shfl_xor_sync(0xffffffffu, acc0, 1);
    acc0 += __shfl_xor_sync(0xffffffffu, acc0, 2);
    acc1 += __shfl_xor_sync(0xffffffffu, acc1, 1);
    acc1 += __shfl_xor_sync(0xffffffffu, acc1, 2);

    if (tg == 0) {
        if (tok0 < ntok) out[tok0] = SCALE * acc0;
        if (tok1 < ntok) out[tok1] = SCALE * acc1;
    }
}

extern "C" void kernel_launch(void* const* d_in, const int* in_sizes, int n_in,
                              void* d_out, int out_size) {
    // Identify S by element count (NPROJ*DIM = 32768); q precedes k among the rest.
    int s_idx = 2;
    for (int i = 0; i < n_in; ++i) if (in_sizes[i] == NPROJ * DIM) { s_idx = i; break; }
    int qk[2], wcnt = 0;
    for (int i = 0; i < n_in && wcnt < 2; ++i) if (i != s_idx) qk[wcnt++] = i;

    const float* Q = (const float*)d_in[qk[0]];  // query [B,H,SEQ,DIM] fp32
    const float* K = (const float*)d_in[qk[1]];  // key   [B,H,SEQ,DIM] fp32
    const float* S = (const float*)d_in[s_idx];  // S     [NPROJ,DIM]   fp32
    float* out = (float*)d_out;                  // [B,H,SEQ] fp32

    const int ntok   = in_sizes[qk[0]] / DIM;
    const int blocks = (ntok + TOK_PER_CTA - 1) / TOK_PER_CTA;

    prep_S<<<32, 256>>>(S);
    qjl_mma_kernel<<<blocks, TPB>>>(Q, K, S, out, ntok);
}